// round 11
// baseline (speedup 1.0000x reference)
#include <cuda_runtime.h>

#define EMBED   1024
#define EPB     8
#define NB      64
#define KTOP    2
#define SPLIT   8
#define CAP     2048

// ---------------------------------------------------------------------------
// Fused router. One block per (bucket, slice). 2 tokens per warp pass.
// vals[32] packs dots AND h-norms: [t*16+e]=dot(t,e), [t*16+8]=||h_t||^2.
// One 31-shuffle reduce-scatter lands value L fully-summed on lane L
// (mapping verified in R10). Parallel epilogue on two 16-lane groups.
// Output f32: out[0:ntok*K]=gid, out[ntok*K:2*ntok*K]=w.
// ---------------------------------------------------------------------------
__global__ __launch_bounds__(256, 3) void router_kernel(
    const float* __restrict__ h,
    const void*  __restrict__ op_raw,
    const float* __restrict__ key,
    float*       __restrict__ out,
    int ntok)
{
    __shared__ float          skey[EPB * EMBED];   // 32 KB
    __shared__ unsigned short slist[CAP];          // 4 KB
    __shared__ int            scount;
    __shared__ int            any_nz;

    const int bucket = blockIdx.x / SPLIT;
    const int slice  = blockIdx.x % SPLIT;
    const int tid    = threadIdx.x;
    const int wid    = tid >> 5;
    const int lane   = tid & 31;
    const unsigned FULL = 0xffffffffu;

    if (tid == 0) { scount = 0; any_nz = 0; }
    __syncthreads();

    // --- dtype probe: int64 LE op_id => odd 32-bit words all zero.
    {
        const int* op32 = (const int*)op_raw;
        if (tid < 64 && (2 * tid + 1) < ntok)
            if (op32[2 * tid + 1] != 0) atomicOr(&any_nz, 1);
    }

    // --- stage this bucket's raw keys (float4)
    const float4* kg = (const float4*)(key + (size_t)bucket * EPB * EMBED);
    float4*       ks = (float4*)skey;
    #pragma unroll
    for (int r = 0; r < 8; r++) ks[tid + 256 * r] = kg[tid + 256 * r];
    __syncthreads();

    const int is64 = any_nz ? 0 : 1;

    // --- scan contiguous token slice, collect matches
    {
        const int cands  = (ntok + SPLIT - 1) / SPLIT;
        const int tstart = slice * cands;
        const int tend   = (tstart + cands < ntok) ? (tstart + cands) : ntok;
        for (int t = tstart + tid; t < tend; t += 256) {
            long long v = is64 ? ((const long long*)op_raw)[t]
                               : (long long)((const int*)op_raw)[t];
            int b = (int)(v < 0 ? 0LL : (v > (NB - 1) ? (long long)(NB - 1) : v));
            if (b == bucket) {
                int p = atomicAdd(&scount, 1);
                if (p < CAP) slist[p] = (unsigned short)t;
            }
        }
    }

    // --- normalize key row `wid` in smem (8 warps = 8 rows)
    {
        float ss = 0.f;
        #pragma unroll
        for (int k = 0; k < 8; k++) {
            float4 v = ks[wid * 256 + k * 32 + lane];
            ss += v.x * v.x + v.y * v.y + v.z * v.z + v.w * v.w;
        }
        #pragma unroll
        for (int o = 16; o; o >>= 1) ss += __shfl_xor_sync(FULL, ss, o);
        float rn = 1.0f / fmaxf(sqrtf(ss), 1e-12f);
        #pragma unroll
        for (int k = 0; k < 8; k++) {
            float4 v = ks[wid * 256 + k * 32 + lane];
            v.x *= rn; v.y *= rn; v.z *= rn; v.w *= rn;
            ks[wid * 256 + k * 32 + lane] = v;
        }
    }
    __syncthreads();

    const int count = scount < CAP ? scount : CAP;
    const int btk   = ntok * KTOP;
    const float4* h4p = (const float4*)h;

    for (int base = wid * 2; base < count; base += 8 * 2) {
        const int t0 = (int)slist[(base + 0) < count ? base + 0 : base];
        const int t1 = (int)slist[(base + 1) < count ? base + 1 : base];

        float vals[32];
        #pragma unroll
        for (int v = 0; v < 32; v++) vals[v] = 0.f;

        #pragma unroll
        for (int c = 0; c < 8; c++) {
            float4 hv0 = h4p[(size_t)t0 * (EMBED / 4) + c * 32 + lane];
            float4 hv1 = h4p[(size_t)t1 * (EMBED / 4) + c * 32 + lane];

            vals[8]  += hv0.x * hv0.x + hv0.y * hv0.y + hv0.z * hv0.z + hv0.w * hv0.w;
            vals[24] += hv1.x * hv1.x + hv1.y * hv1.y + hv1.z * hv1.z + hv1.w * hv1.w;

            #pragma unroll
            for (int e = 0; e < EPB; e++) {
                float4 k4 = ks[e * (EMBED / 4) + c * 32 + lane];
                vals[e]      += hv0.x * k4.x + hv0.y * k4.y + hv0.z * k4.z + hv0.w * k4.w;
                vals[16 + e] += hv1.x * k4.x + hv1.y * k4.y + hv1.z * k4.z + hv1.w * k4.w;
            }
        }

        // Reduce-scatter: lane L ends with the full sum of vals index L.
        #pragma unroll
        for (int s = 16; s >= 1; s >>= 1) {
            #pragma unroll
            for (int k = 0; k < s; k++) {
                bool  up   = (lane & s) != 0;
                float give = up ? vals[k] : vals[k + s];
                float keep = up ? vals[k + s] : vals[k];
                float recv = __shfl_xor_sync(FULL, give, s);
                vals[k] = keep + recv;
            }
        }

        // ---- parallel epilogue: lane group g=lane>>4 = token, e=lane&7
        const int le   = lane & 15;
        const int e    = lane & 7;
        const int idx  = base + (lane >> 4);
        const bool valid = (idx < count) && (le < 8);

        // broadcast this token's ||h||^2 from lane (g*16 + 8)
        float hsel = __shfl_sync(FULL, vals[0], (lane & 16) | 8);
        float rh = 1.0f / fmaxf(sqrtf(hsel), 1e-12f);
        float sc = vals[0] * rh;                       // TAU = 1.0

        // softmax within 8-lane subgroup (lanes with le<8 are coherent)
        float m = sc;
        #pragma unroll
        for (int o = 4; o; o >>= 1) m = fmaxf(m, __shfl_xor_sync(FULL, m, o));
        float p = __expf(sc - m);
        float Z = p;
        #pragma unroll
        for (int o = 4; o; o >>= 1) Z += __shfl_xor_sync(FULL, Z, o);

        // top-1 (max prob, lowest index on ties)
        float bv = p; int be = e;
        #pragma unroll
        for (int o = 4; o; o >>= 1) {
            float ov = __shfl_xor_sync(FULL, bv, o);
            int   oe = __shfl_xor_sync(FULL, be, o);
            if (ov > bv || (ov == bv && oe < be)) { bv = ov; be = oe; }
        }
        // top-2: exclude top-1
        float p2 = (e == be) ? -1.f : p;
        float bv2 = p2; int be2 = e;
        #pragma unroll
        for (int o = 4; o; o >>= 1) {
            float ov = __shfl_xor_sync(FULL, bv2, o);
            int   oe = __shfl_xor_sync(FULL, be2, o);
            if (ov > bv2 || (ov == bv2 && oe < be2)) { bv2 = ov; be2 = oe; }
        }

        if (le == 0 && valid) {
            int tt = (int)slist[idx];
            float v1 = bv / Z, v2 = bv2 / Z;
            float ws = v1 + v2 + 1e-9f;
            ((float2*)out)[tt]         = make_float2((float)(bucket * EPB + be),
                                                     (float)(bucket * EPB + be2));
            ((float2*)(out + btk))[tt] = make_float2(v1 / ws, v2 / ws);
        }
    }
}

// ---------------------------------------------------------------------------
extern "C" void kernel_launch(void* const* d_in, const int* in_sizes, int n_in,
                              void* d_out, int out_size)
{
    const float* h   = (const float*)d_in[0];
    const void*  op  = d_in[1];
    const float* key = (const float*)d_in[2];
    float*       out = (float*)d_out;
    int ntok = in_sizes[1];

    router_kernel<<<NB * SPLIT, 256>>>(h, op, key, out, ntok);
}

// round 13
// speedup vs baseline: 1.0313x; 1.0313x over previous
#include <cuda_runtime.h>

#define EMBED   1024
#define EPB     8
#define NB      64
#define KTOP    2
#define SPLIT   8
#define CAP     2048

// ---------------------------------------------------------------------------
// Fused router. One block per (bucket, slice). ONE token per warp pass:
// vals[16] = {dot(e=0..7), ||h||^2, 0...}. Live set ~40 regs => no spills
// under the 64-reg cap of (256,4) -> 4 blocks/SM.
// Reduction: 16-SHFL butterfly stage + 15-SHFL reduce-scatter; lane L ends
// with full sum of vals[L] (L<16; lanes 16-31 mirror). Parallel epilogue
// (proven in R10/R11): softmax+top2 on 8-lane subgroup, write from lane 0.
// Output f32: out[0:ntok*K]=gid, out[ntok*K:2*ntok*K]=w.
// ---------------------------------------------------------------------------
__global__ __launch_bounds__(256, 4) void router_kernel(
    const float* __restrict__ h,
    const void*  __restrict__ op_raw,
    const float* __restrict__ key,
    float*       __restrict__ out,
    int ntok)
{
    __shared__ float          skey[EPB * EMBED];   // 32 KB
    __shared__ unsigned short slist[CAP];          // 4 KB
    __shared__ int            scount;
    __shared__ int            any_nz;

    const int bucket = blockIdx.x / SPLIT;
    const int slice  = blockIdx.x % SPLIT;
    const int tid    = threadIdx.x;
    const int wid    = tid >> 5;
    const int lane   = tid & 31;
    const unsigned FULL = 0xffffffffu;

    if (tid == 0) { scount = 0; any_nz = 0; }
    __syncthreads();

    // --- dtype probe: int64 LE op_id => odd 32-bit words all zero.
    {
        const int* op32 = (const int*)op_raw;
        if (tid < 64 && (2 * tid + 1) < ntok)
            if (op32[2 * tid + 1] != 0) atomicOr(&any_nz, 1);
    }

    // --- stage this bucket's raw keys (float4)
    const float4* kg = (const float4*)(key + (size_t)bucket * EPB * EMBED);
    float4*       ks = (float4*)skey;
    #pragma unroll
    for (int r = 0; r < 8; r++) ks[tid + 256 * r] = kg[tid + 256 * r];
    __syncthreads();

    const int is64 = any_nz ? 0 : 1;

    // --- scan contiguous token slice, collect matches
    {
        const int cands  = (ntok + SPLIT - 1) / SPLIT;
        const int tstart = slice * cands;
        const int tend   = (tstart + cands < ntok) ? (tstart + cands) : ntok;
        for (int t = tstart + tid; t < tend; t += 256) {
            long long v = is64 ? ((const long long*)op_raw)[t]
                               : (long long)((const int*)op_raw)[t];
            int b = (int)(v < 0 ? 0LL : (v > (NB - 1) ? (long long)(NB - 1) : v));
            if (b == bucket) {
                int p = atomicAdd(&scount, 1);
                if (p < CAP) slist[p] = (unsigned short)t;
            }
        }
    }

    // --- normalize key row `wid` in smem (8 warps = 8 rows)
    {
        float ss = 0.f;
        #pragma unroll
        for (int k = 0; k < 8; k++) {
            float4 v = ks[wid * 256 + k * 32 + lane];
            ss += v.x * v.x + v.y * v.y + v.z * v.z + v.w * v.w;
        }
        #pragma unroll
        for (int o = 16; o; o >>= 1) ss += __shfl_xor_sync(FULL, ss, o);
        float rn = 1.0f / fmaxf(sqrtf(ss), 1e-12f);
        #pragma unroll
        for (int k = 0; k < 8; k++) {
            float4 v = ks[wid * 256 + k * 32 + lane];
            v.x *= rn; v.y *= rn; v.z *= rn; v.w *= rn;
            ks[wid * 256 + k * 32 + lane] = v;
        }
    }
    __syncthreads();

    const int count = scount < CAP ? scount : CAP;
    const int btk   = ntok * KTOP;
    const float4* h4p = (const float4*)h;

    for (int base = wid; base < count; base += 8) {
        const int t0 = (int)slist[base];

        float vals[16];
        #pragma unroll
        for (int v = 0; v < 16; v++) vals[v] = 0.f;

        #pragma unroll
        for (int c = 0; c < 8; c++) {
            float4 hv = h4p[(size_t)t0 * (EMBED / 4) + c * 32 + lane];
            vals[8] += hv.x * hv.x + hv.y * hv.y + hv.z * hv.z + hv.w * hv.w;
            #pragma unroll
            for (int e = 0; e < EPB; e++) {
                float4 k4 = ks[e * (EMBED / 4) + c * 32 + lane];
                vals[e] += hv.x * k4.x + hv.y * k4.y + hv.z * k4.z + hv.w * k4.w;
            }
        }

        // Stage 1: butterfly-add across half-warps (16 values, 16 SHFL)
        #pragma unroll
        for (int k = 0; k < 16; k++)
            vals[k] += __shfl_xor_sync(FULL, vals[k], 16);
        // Stage 2: reduce-scatter within 16 lanes (15 SHFL); lane L -> vals[L]
        #pragma unroll
        for (int s = 8; s >= 1; s >>= 1) {
            #pragma unroll
            for (int k = 0; k < s; k++) {
                bool  up   = (lane & s) != 0;
                float give = up ? vals[k] : vals[k + s];
                float keep = up ? vals[k + s] : vals[k];
                float recv = __shfl_xor_sync(FULL, give, s);
                vals[k] = keep + recv;
            }
        }

        // ---- parallel epilogue: lanes 0-7 hold dots, lane 8 holds ||h||^2
        const int e = lane & 7;

        float hsel = __shfl_sync(FULL, vals[0], 8);
        float rh = 1.0f / fmaxf(sqrtf(hsel), 1e-12f);
        float sc = vals[0] * rh;                       // TAU = 1.0

        // softmax within 8-lane subgroup
        float m = sc;
        #pragma unroll
        for (int o = 4; o; o >>= 1) m = fmaxf(m, __shfl_xor_sync(FULL, m, o));
        float p = __expf(sc - m);
        float Z = p;
        #pragma unroll
        for (int o = 4; o; o >>= 1) Z += __shfl_xor_sync(FULL, Z, o);

        // top-1 (max prob, lowest index on ties)
        float bv = p; int be = e;
        #pragma unroll
        for (int o = 4; o; o >>= 1) {
            float ov = __shfl_xor_sync(FULL, bv, o);
            int   oe = __shfl_xor_sync(FULL, be, o);
            if (ov > bv || (ov == bv && oe < be)) { bv = ov; be = oe; }
        }
        // top-2: exclude top-1
        float p2 = (e == be) ? -1.f : p;
        float bv2 = p2; int be2 = e;
        #pragma unroll
        for (int o = 4; o; o >>= 1) {
            float ov = __shfl_xor_sync(FULL, bv2, o);
            int   oe = __shfl_xor_sync(FULL, be2, o);
            if (ov > bv2 || (ov == bv2 && oe < be2)) { bv2 = ov; be2 = oe; }
        }

        if (lane == 0) {
            float v1 = bv / Z, v2 = bv2 / Z;
            float ws = v1 + v2 + 1e-9f;
            ((float2*)out)[t0]         = make_float2((float)(bucket * EPB + be),
                                                     (float)(bucket * EPB + be2));
            ((float2*)(out + btk))[t0] = make_float2(v1 / ws, v2 / ws);
        }
    }
}

// ---------------------------------------------------------------------------
extern "C" void kernel_launch(void* const* d_in, const int* in_sizes, int n_in,
                              void* d_out, int out_size)
{
    const float* h   = (const float*)d_in[0];
    const void*  op  = d_in[1];
    const float* key = (const float*)d_in[2];
    float*       out = (float*)d_out;
    int ntok = in_sizes[1];

    router_kernel<<<NB * SPLIT, 256>>>(h, op, key, out, ntok);
}

// round 15
// speedup vs baseline: 3.3582x; 3.2562x over previous
#include <cuda_runtime.h>

#define EMBED   1024
#define EPB     8
#define NB      64
#define KTOP    2
#define SPLIT   8
#define CAP     2048

// ---------------------------------------------------------------------------
// Fused router. One block per (bucket, slice). ONE token per warp pass.
// vals[16] = {dot(e=0..7), ||h||^2, 0...}.
// KEY CHANGE vs R13: '#pragma unroll 2' on the chunk loop stops ptxas from
// front-hoisting all 8 h-row loads (32 regs) which, under the 64-reg cap,
// forced accumulator spills (519MB DRAM traffic measured in R13).
// Reduction + parallel epilogue numerically proven in R10-R13 (rel_err 6.7e-8).
// Output f32: out[0:ntok*K]=gid, out[ntok*K:2*ntok*K]=w.
// ---------------------------------------------------------------------------
__global__ __launch_bounds__(256, 4) void router_kernel(
    const float* __restrict__ h,
    const void*  __restrict__ op_raw,
    const float* __restrict__ key,
    float*       __restrict__ out,
    int ntok)
{
    __shared__ float          skey[EPB * EMBED];   // 32 KB
    __shared__ unsigned short slist[CAP];          // 4 KB
    __shared__ int            scount;
    __shared__ int            any_nz;

    const int bucket = blockIdx.x / SPLIT;
    const int slice  = blockIdx.x % SPLIT;
    const int tid    = threadIdx.x;
    const int wid    = tid >> 5;
    const int lane   = tid & 31;
    const unsigned FULL = 0xffffffffu;

    if (tid == 0) { scount = 0; any_nz = 0; }
    __syncthreads();

    // --- dtype probe: int64 LE op_id => odd 32-bit words all zero.
    {
        const int* op32 = (const int*)op_raw;
        if (tid < 64 && (2 * tid + 1) < ntok)
            if (op32[2 * tid + 1] != 0) atomicOr(&any_nz, 1);
    }

    // --- stage this bucket's raw keys (float4)
    const float4* kg = (const float4*)(key + (size_t)bucket * EPB * EMBED);
    float4*       ks = (float4*)skey;
    #pragma unroll
    for (int r = 0; r < 8; r++) ks[tid + 256 * r] = kg[tid + 256 * r];
    __syncthreads();

    const int is64 = any_nz ? 0 : 1;

    // --- scan contiguous token slice, collect matches
    {
        const int cands  = (ntok + SPLIT - 1) / SPLIT;
        const int tstart = slice * cands;
        const int tend   = (tstart + cands < ntok) ? (tstart + cands) : ntok;
        for (int t = tstart + tid; t < tend; t += 256) {
            long long v = is64 ? ((const long long*)op_raw)[t]
                               : (long long)((const int*)op_raw)[t];
            int b = (int)(v < 0 ? 0LL : (v > (NB - 1) ? (long long)(NB - 1) : v));
            if (b == bucket) {
                int p = atomicAdd(&scount, 1);
                if (p < CAP) slist[p] = (unsigned short)t;
            }
        }
    }

    // --- normalize key row `wid` in smem (8 warps = 8 rows)
    {
        float ss = 0.f;
        #pragma unroll
        for (int k = 0; k < 8; k++) {
            float4 v = ks[wid * 256 + k * 32 + lane];
            ss += v.x * v.x + v.y * v.y + v.z * v.z + v.w * v.w;
        }
        #pragma unroll
        for (int o = 16; o; o >>= 1) ss += __shfl_xor_sync(FULL, ss, o);
        float rn = 1.0f / fmaxf(sqrtf(ss), 1e-12f);
        #pragma unroll
        for (int k = 0; k < 8; k++) {
            float4 v = ks[wid * 256 + k * 32 + lane];
            v.x *= rn; v.y *= rn; v.z *= rn; v.w *= rn;
            ks[wid * 256 + k * 32 + lane] = v;
        }
    }
    __syncthreads();

    const int count = scount < CAP ? scount : CAP;
    const int btk   = ntok * KTOP;
    const float4* h4p = (const float4*)h;

    for (int base = wid; base < count; base += 8) {
        const int t0 = (int)slist[base];
        const float4* hrow = h4p + (size_t)t0 * (EMBED / 4) + lane;

        float vals[16];
        #pragma unroll
        for (int v = 0; v < 16; v++) vals[v] = 0.f;

        #pragma unroll 2
        for (int c = 0; c < 8; c++) {
            float4 hv = hrow[c * 32];
            vals[8] += hv.x * hv.x + hv.y * hv.y + hv.z * hv.z + hv.w * hv.w;
            #pragma unroll
            for (int e = 0; e < EPB; e++) {
                float4 k4 = ks[e * (EMBED / 4) + c * 32 + lane];
                vals[e] += hv.x * k4.x + hv.y * k4.y + hv.z * k4.z + hv.w * k4.w;
            }
        }

        // Stage 1: butterfly-add across half-warps (16 values, 16 SHFL)
        #pragma unroll
        for (int k = 0; k < 16; k++)
            vals[k] += __shfl_xor_sync(FULL, vals[k], 16);
        // Stage 2: reduce-scatter within 16 lanes (15 SHFL); lane L -> vals[L]
        #pragma unroll
        for (int s = 8; s >= 1; s >>= 1) {
            #pragma unroll
            for (int k = 0; k < s; k++) {
                bool  up   = (lane & s) != 0;
                float give = up ? vals[k] : vals[k + s];
                float keep = up ? vals[k + s] : vals[k];
                float recv = __shfl_xor_sync(FULL, give, s);
                vals[k] = keep + recv;
            }
        }

        // ---- parallel epilogue: lanes 0-7 hold dots, lane 8 holds ||h||^2
        const int e = lane & 7;

        float hsel = __shfl_sync(FULL, vals[0], 8);
        float rh = 1.0f / fmaxf(sqrtf(hsel), 1e-12f);
        float sc = vals[0] * rh;                       // TAU = 1.0

        // softmax within 8-lane subgroup
        float m = sc;
        #pragma unroll
        for (int o = 4; o; o >>= 1) m = fmaxf(m, __shfl_xor_sync(FULL, m, o));
        float p = __expf(sc - m);
        float Z = p;
        #pragma unroll
        for (int o = 4; o; o >>= 1) Z += __shfl_xor_sync(FULL, Z, o);

        // top-1 (max prob, lowest index on ties)
        float bv = p; int be = e;
        #pragma unroll
        for (int o = 4; o; o >>= 1) {
            float ov = __shfl_xor_sync(FULL, bv, o);
            int   oe = __shfl_xor_sync(FULL, be, o);
            if (ov > bv || (ov == bv && oe < be)) { bv = ov; be = oe; }
        }
        // top-2: exclude top-1
        float p2 = (e == be) ? -1.f : p;
        float bv2 = p2; int be2 = e;
        #pragma unroll
        for (int o = 4; o; o >>= 1) {
            float ov = __shfl_xor_sync(FULL, bv2, o);
            int   oe = __shfl_xor_sync(FULL, be2, o);
            if (ov > bv2 || (ov == bv2 && oe < be2)) { bv2 = ov; be2 = oe; }
        }

        if (lane == 0) {
            float v1 = bv / Z, v2 = bv2 / Z;
            float ws = v1 + v2 + 1e-9f;
            ((float2*)out)[t0]         = make_float2((float)(bucket * EPB + be),
                                                     (float)(bucket * EPB + be2));
            ((float2*)(out + btk))[t0] = make_float2(v1 / ws, v2 / ws);
        }
    }
}

// ---------------------------------------------------------------------------
extern "C" void kernel_launch(void* const* d_in, const int* in_sizes, int n_in,
                              void* d_out, int out_size)
{
    const float* h   = (const float*)d_in[0];
    const void*  op  = d_in[1];
    const float* key = (const float*)d_in[2];
    float*       out = (float*)d_out;
    int ntok = in_sizes[1];

    router_kernel<<<NB * SPLIT, 256>>>(h, op, key, out, ntok);
}

// round 16
// speedup vs baseline: 3.9827x; 1.1860x over previous
#include <cuda_runtime.h>

#define EMBED   1024
#define EPB     8
#define NB      64
#define KTOP    2
#define SPLIT   8
#define CAP     2048

// ---------------------------------------------------------------------------
// Fused router. One block per (bucket, slice). TWO tokens per warp pass:
// vals[32]: [t*16+e]=dot(t,e) for e=0..7, [t*16+8]=||h_t||^2 (R11 layout).
// unroll-2 on the chunk loop bounds the LDG hoist (R15's fix); (256,3) caps
// regs at 84 > ~70 live => no spills. 31-SHFL reduce-scatter + two-group
// parallel epilogue, both numerically proven (rel_err 6.7e-8 in R11/R15).
// Output f32: out[0:ntok*K]=gid, out[ntok*K:2*ntok*K]=w.
// ---------------------------------------------------------------------------
__global__ __launch_bounds__(256, 3) void router_kernel(
    const float* __restrict__ h,
    const void*  __restrict__ op_raw,
    const float* __restrict__ key,
    float*       __restrict__ out,
    int ntok)
{
    __shared__ float          skey[EPB * EMBED];   // 32 KB
    __shared__ unsigned short slist[CAP];          // 4 KB
    __shared__ int            scount;
    __shared__ int            any_nz;

    const int bucket = blockIdx.x / SPLIT;
    const int slice  = blockIdx.x % SPLIT;
    const int tid    = threadIdx.x;
    const int wid    = tid >> 5;
    const int lane   = tid & 31;
    const unsigned FULL = 0xffffffffu;

    if (tid == 0) { scount = 0; any_nz = 0; }
    __syncthreads();

    // --- dtype probe: int64 LE op_id => odd 32-bit words all zero.
    {
        const int* op32 = (const int*)op_raw;
        if (tid < 64 && (2 * tid + 1) < ntok)
            if (op32[2 * tid + 1] != 0) atomicOr(&any_nz, 1);
    }

    // --- stage this bucket's raw keys (float4)
    const float4* kg = (const float4*)(key + (size_t)bucket * EPB * EMBED);
    float4*       ks = (float4*)skey;
    #pragma unroll
    for (int r = 0; r < 8; r++) ks[tid + 256 * r] = kg[tid + 256 * r];
    __syncthreads();

    const int is64 = any_nz ? 0 : 1;

    // --- scan contiguous token slice, collect matches
    {
        const int cands  = (ntok + SPLIT - 1) / SPLIT;
        const int tstart = slice * cands;
        const int tend   = (tstart + cands < ntok) ? (tstart + cands) : ntok;
        for (int t = tstart + tid; t < tend; t += 256) {
            long long v = is64 ? ((const long long*)op_raw)[t]
                               : (long long)((const int*)op_raw)[t];
            int b = (int)(v < 0 ? 0LL : (v > (NB - 1) ? (long long)(NB - 1) : v));
            if (b == bucket) {
                int p = atomicAdd(&scount, 1);
                if (p < CAP) slist[p] = (unsigned short)t;
            }
        }
    }

    // --- normalize key row `wid` in smem (8 warps = 8 rows)
    {
        float ss = 0.f;
        #pragma unroll
        for (int k = 0; k < 8; k++) {
            float4 v = ks[wid * 256 + k * 32 + lane];
            ss += v.x * v.x + v.y * v.y + v.z * v.z + v.w * v.w;
        }
        #pragma unroll
        for (int o = 16; o; o >>= 1) ss += __shfl_xor_sync(FULL, ss, o);
        float rn = 1.0f / fmaxf(sqrtf(ss), 1e-12f);
        #pragma unroll
        for (int k = 0; k < 8; k++) {
            float4 v = ks[wid * 256 + k * 32 + lane];
            v.x *= rn; v.y *= rn; v.z *= rn; v.w *= rn;
            ks[wid * 256 + k * 32 + lane] = v;
        }
    }
    __syncthreads();

    const int count = scount < CAP ? scount : CAP;
    const int btk   = ntok * KTOP;
    const float4* h4p = (const float4*)h;

    for (int base = wid * 2; base < count; base += 8 * 2) {
        const int t0 = (int)slist[(base + 0) < count ? base + 0 : base];
        const int t1 = (int)slist[(base + 1) < count ? base + 1 : base];
        const float4* hrow0 = h4p + (size_t)t0 * (EMBED / 4) + lane;
        const float4* hrow1 = h4p + (size_t)t1 * (EMBED / 4) + lane;

        float vals[32];
        #pragma unroll
        for (int v = 0; v < 32; v++) vals[v] = 0.f;

        #pragma unroll 2
        for (int c = 0; c < 8; c++) {
            float4 hv0 = hrow0[c * 32];
            float4 hv1 = hrow1[c * 32];
            vals[8]  += hv0.x * hv0.x + hv0.y * hv0.y + hv0.z * hv0.z + hv0.w * hv0.w;
            vals[24] += hv1.x * hv1.x + hv1.y * hv1.y + hv1.z * hv1.z + hv1.w * hv1.w;
            #pragma unroll
            for (int e = 0; e < EPB; e++) {
                float4 k4 = ks[e * (EMBED / 4) + c * 32 + lane];
                vals[e]      += hv0.x * k4.x + hv0.y * k4.y + hv0.z * k4.z + hv0.w * k4.w;
                vals[16 + e] += hv1.x * k4.x + hv1.y * k4.y + hv1.z * k4.z + hv1.w * k4.w;
            }
        }

        // Reduce-scatter: lane L ends with the full sum of vals index L.
        #pragma unroll
        for (int s = 16; s >= 1; s >>= 1) {
            #pragma unroll
            for (int k = 0; k < s; k++) {
                bool  up   = (lane & s) != 0;
                float give = up ? vals[k] : vals[k + s];
                float keep = up ? vals[k + s] : vals[k];
                float recv = __shfl_xor_sync(FULL, give, s);
                vals[k] = keep + recv;
            }
        }

        // ---- parallel epilogue: group g=lane>>4 = token, e=lane&7
        const int le   = lane & 15;
        const int e    = lane & 7;
        const int idx  = base + (lane >> 4);
        const bool valid = (idx < count) && (le < 8);

        // broadcast this token's ||h||^2 from lane (g*16 + 8)
        float hsel = __shfl_sync(FULL, vals[0], (lane & 16) | 8);
        float rh = 1.0f / fmaxf(sqrtf(hsel), 1e-12f);
        float sc = vals[0] * rh;                       // TAU = 1.0

        // softmax within 8-lane subgroup
        float m = sc;
        #pragma unroll
        for (int o = 4; o; o >>= 1) m = fmaxf(m, __shfl_xor_sync(FULL, m, o));
        float p = __expf(sc - m);
        float Z = p;
        #pragma unroll
        for (int o = 4; o; o >>= 1) Z += __shfl_xor_sync(FULL, Z, o);

        // top-1 (max prob, lowest index on ties)
        float bv = p; int be = e;
        #pragma unroll
        for (int o = 4; o; o >>= 1) {
            float ov = __shfl_xor_sync(FULL, bv, o);
            int   oe = __shfl_xor_sync(FULL, be, o);
            if (ov > bv || (ov == bv && oe < be)) { bv = ov; be = oe; }
        }
        // top-2: exclude top-1
        float p2 = (e == be) ? -1.f : p;
        float bv2 = p2; int be2 = e;
        #pragma unroll
        for (int o = 4; o; o >>= 1) {
            float ov = __shfl_xor_sync(FULL, bv2, o);
            int   oe = __shfl_xor_sync(FULL, be2, o);
            if (ov > bv2 || (ov == bv2 && oe < be2)) { bv2 = ov; be2 = oe; }
        }

        if (le == 0 && valid) {
            int tt = (int)slist[idx];
            float v1 = bv / Z, v2 = bv2 / Z;
            float ws = v1 + v2 + 1e-9f;
            ((float2*)out)[tt]         = make_float2((float)(bucket * EPB + be),
                                                     (float)(bucket * EPB + be2));
            ((float2*)(out + btk))[tt] = make_float2(v1 / ws, v2 / ws);
        }
    }
}

// ---------------------------------------------------------------------------
extern "C" void kernel_launch(void* const* d_in, const int* in_sizes, int n_in,
                              void* d_out, int out_size)
{
    const float* h   = (const float*)d_in[0];
    const void*  op  = d_in[1];
    const float* key = (const float*)d_in[2];
    float*       out = (float*)d_out;
    int ntok = in_sizes[1];

    router_kernel<<<NB * SPLIT, 256>>>(h, op, key, out, ntok);
}